// round 4
// baseline (speedup 1.0000x reference)
#include <cuda_runtime.h>
#include <cstdint>
#include <cstddef>

// Scatter-mean message passing via single-pass padded-CSR build + per-node gather-reduce.
//   out[t] = mean over edges e with tgt[e]==t of x[src[e]]
// x: [N, 64] f32, edge_idx: [2, E] i32 (row 0 = src, row 1 = tgt)

#define F 64
#define MAX_N (1 << 17)      // >= 100000
#define SLOTS 64             // padded CSR row capacity (Poisson(16): P(deg>64) ~ 1e-20)
#define MAX_OVER 8192        // overflow spill capacity (correctness fallback)

typedef unsigned long long ull;

__device__ int g_cnt[MAX_N];                     // per-node edge count (true degree)
__device__ int g_sorted[(size_t)MAX_N * SLOTS];  // per-node src BYTE OFFSETS (src*256)
__device__ int g_over_src[MAX_OVER];             // overflow: src byte offsets
__device__ int g_over_tgt[MAX_OVER];
__device__ int g_over_cnt[1];

__device__ __forceinline__ void place_edge(int s, int d) {
    int pos = atomicAdd(&g_cnt[d], 1);
    int soff = s << 8;                           // pre-scaled byte offset (row = 256B)
    if (pos < SLOTS) {
        g_sorted[(size_t)d * SLOTS + pos] = soff;
    } else {
        int op = atomicAdd(&g_over_cnt[0], 1);
        if (op < MAX_OVER) { g_over_src[op] = soff; g_over_tgt[op] = d; }
    }
}

// Single build pass: 4 edges per thread via int4.
__global__ void fill_kernel(const int4* __restrict__ src4,
                            const int4* __restrict__ tgt4, int E4,
                            const int* __restrict__ src,
                            const int* __restrict__ tgt, int E) {
    int t = blockIdx.x * blockDim.x + threadIdx.x;
    if (t < E4) {
        int4 s = __ldg(&src4[t]);
        int4 d = __ldg(&tgt4[t]);
        place_edge(s.x, d.x);
        place_edge(s.y, d.y);
        place_edge(s.z, d.z);
        place_edge(s.w, d.w);
    }
    if (t == 0) {
        for (int e = E4 * 4; e < E; e++) place_edge(src[e], tgt[e]);
    }
}

__device__ __forceinline__ ull f2add(ull a, ull b) {
    ull r;
    asm("add.rn.f32x2 %0, %1, %2;" : "=l"(r) : "l"(a), "l"(b));
    return r;
}
__device__ __forceinline__ ull f2mul(ull a, ull b) {
    ull r;
    asm("mul.rn.f32x2 %0, %1, %2;" : "=l"(r) : "l"(a), "l"(b));
    return r;
}

// One warp per node. Half-warp per edge: lanes 0-15 take even edges, 16-31 odd.
// Each lane owns 16B (float4) of the 256B row -> one LDG.128 gathers a full row
// per half-warp. ~2.5 warp-instructions per edge, 8 gathers in flight.
__global__ void __launch_bounds__(256)
aggregate_kernel(const char* __restrict__ xbase,
                 ulonglong2* __restrict__ out, int N) {
    int n = (blockIdx.x * blockDim.x + threadIdx.x) >> 5;
    int lane = threadIdx.x & 31;
    if (n >= N) return;

    int hi = lane >> 4;          // which edge of the pair
    int sub = lane & 15;         // 16B chunk within row
    int count = g_cnt[n];
    int m = count < SLOTS ? count : SLOTS;
    const int* row = &g_sorted[(size_t)n * SLOTS];
    const char* xoff = xbase + (sub << 4);

    ull a0 = 0, a1 = 0, b0 = 0, b1 = 0, c0 = 0, c1 = 0, d0 = 0, d1 = 0;

    int e = 0;
    for (; e + 8 <= m; e += 8) {
        int s0 = __ldg(&row[e + 0 + hi]);
        int s1 = __ldg(&row[e + 2 + hi]);
        int s2 = __ldg(&row[e + 4 + hi]);
        int s3 = __ldg(&row[e + 6 + hi]);
        ulonglong2 v0 = __ldg((const ulonglong2*)(xoff + (size_t)(unsigned)s0));
        ulonglong2 v1 = __ldg((const ulonglong2*)(xoff + (size_t)(unsigned)s1));
        ulonglong2 v2 = __ldg((const ulonglong2*)(xoff + (size_t)(unsigned)s2));
        ulonglong2 v3 = __ldg((const ulonglong2*)(xoff + (size_t)(unsigned)s3));
        a0 = f2add(a0, v0.x); a1 = f2add(a1, v0.y);
        b0 = f2add(b0, v1.x); b1 = f2add(b1, v1.y);
        c0 = f2add(c0, v2.x); c1 = f2add(c1, v2.y);
        d0 = f2add(d0, v3.x); d1 = f2add(d1, v3.y);
    }
    for (; e + 2 <= m; e += 2) {
        int s = __ldg(&row[e + hi]);
        ulonglong2 v = __ldg((const ulonglong2*)(xoff + (size_t)(unsigned)s));
        a0 = f2add(a0, v.x); a1 = f2add(a1, v.y);
    }
    if (e < m && hi == 0) {      // odd tail edge: low half only
        int s = __ldg(&row[e]);
        ulonglong2 v = __ldg((const ulonglong2*)(xoff + (size_t)(unsigned)s));
        a0 = f2add(a0, v.x); a1 = f2add(a1, v.y);
    }

    // Overflow fallback (cold): low half processes, counted once after combine.
    if (count > SLOTS && hi == 0) {
        int oc = g_over_cnt[0];
        for (int i = 0; i < oc; i++) {
            if (g_over_tgt[i] == n) {
                int s = g_over_src[i];
                ulonglong2 v = __ldg((const ulonglong2*)(xoff + (size_t)(unsigned)s));
                a0 = f2add(a0, v.x); a1 = f2add(a1, v.y);
            }
        }
    }

    a0 = f2add(f2add(a0, b0), f2add(c0, d0));
    a1 = f2add(f2add(a1, b1), f2add(c1, d1));

    // combine the two half-warps (same features, different edges)
    a0 = f2add(a0, __shfl_xor_sync(0xffffffffu, a0, 16));
    a1 = f2add(a1, __shfl_xor_sync(0xffffffffu, a1, 16));

    if (hi == 0) {
        float inv = count > 0 ? 1.0f / (float)count : 0.0f;
        ull inv2;
        asm("mov.b64 %0, {%1, %1};" : "=l"(inv2) : "f"(inv));
        ulonglong2 o;
        o.x = f2mul(a0, inv2);
        o.y = f2mul(a1, inv2);
        out[(size_t)n * 16 + sub] = o;
    }
}

extern "C" void kernel_launch(void* const* d_in, const int* in_sizes, int n_in,
                              void* d_out, int out_size) {
    const float* x = (const float*)d_in[0];
    const int* edge_idx = (const int*)d_in[1];

    int E = in_sizes[1] / 2;
    int N = out_size / F;

    const int* src = edge_idx;       // row 0
    const int* tgt = edge_idx + E;   // row 1

    // Zero scratch counters via memset nodes.
    void* cnt_ptr = nullptr;
    void* over_ptr = nullptr;
    cudaGetSymbolAddress(&cnt_ptr, g_cnt);
    cudaGetSymbolAddress(&over_ptr, g_over_cnt);
    cudaMemsetAsync(cnt_ptr, 0, (size_t)N * sizeof(int));
    cudaMemsetAsync(over_ptr, 0, sizeof(int));

    const int T = 256;

    int E4 = E / 4;
    int fill_blocks = (E4 + T - 1) / T;
    if (fill_blocks < 1) fill_blocks = 1;
    fill_kernel<<<fill_blocks, T>>>((const int4*)src, (const int4*)tgt, E4,
                                    src, tgt, E);

    long long total = (long long)N * 32;
    aggregate_kernel<<<(int)((total + T - 1) / T), T>>>(
        (const char*)x, (ulonglong2*)d_out, N);
}

// round 5
// speedup vs baseline: 1.0294x; 1.0294x over previous
#include <cuda_runtime.h>
#include <cstdint>
#include <cstddef>

// Scatter-mean message passing via single-pass padded-CSR build + per-node gather-reduce.
//   out[t] = mean over edges e with tgt[e]==t of x[src[e]]
// x: [N, 64] f32, edge_idx: [2, E] i32 (row 0 = src, row 1 = tgt)

#define F 64
#define MAX_N (1 << 17)      // >= 100000
#define SLOTS 64             // padded CSR row capacity (Poisson(16): P(deg>64) ~ 1e-20)
#define MAX_OVER 8192        // overflow spill capacity (correctness fallback)

typedef unsigned long long ull;

__device__ int g_cnt[MAX_N];                     // per-node edge count (true degree)
__device__ int g_sorted[(size_t)MAX_N * SLOTS];  // per-node src BYTE OFFSETS (src*256)
__device__ int g_over_src[MAX_OVER];             // overflow: src byte offsets
__device__ int g_over_tgt[MAX_OVER];
__device__ int g_over_cnt[1];

__device__ __forceinline__ void spill_edge(int soff, int d) {
    int op = atomicAdd(&g_over_cnt[0], 1);
    if (op < MAX_OVER) { g_over_src[op] = soff; g_over_tgt[op] = d; }
}

// Single build pass: 4 edges per thread via int4; 4 atomics issued before the
// 4 dependent scattered stores (atomic latency overlapped).
__global__ void fill_kernel(const int4* __restrict__ src4,
                            const int4* __restrict__ tgt4, int E4,
                            const int* __restrict__ src,
                            const int* __restrict__ tgt, int E) {
    int t = blockIdx.x * blockDim.x + threadIdx.x;
    if (t < E4) {
        int4 s = __ldg(&src4[t]);
        int4 d = __ldg(&tgt4[t]);
        int p0 = atomicAdd(&g_cnt[d.x], 1);
        int p1 = atomicAdd(&g_cnt[d.y], 1);
        int p2 = atomicAdd(&g_cnt[d.z], 1);
        int p3 = atomicAdd(&g_cnt[d.w], 1);
        if (p0 < SLOTS) g_sorted[(size_t)d.x * SLOTS + p0] = s.x << 8; else spill_edge(s.x << 8, d.x);
        if (p1 < SLOTS) g_sorted[(size_t)d.y * SLOTS + p1] = s.y << 8; else spill_edge(s.y << 8, d.y);
        if (p2 < SLOTS) g_sorted[(size_t)d.z * SLOTS + p2] = s.z << 8; else spill_edge(s.z << 8, d.z);
        if (p3 < SLOTS) g_sorted[(size_t)d.w * SLOTS + p3] = s.w << 8; else spill_edge(s.w << 8, d.w);
    }
    if (t == 0) {
        for (int e = E4 * 4; e < E; e++) {
            int d = tgt[e];
            int pos = atomicAdd(&g_cnt[d], 1);
            if (pos < SLOTS) g_sorted[(size_t)d * SLOTS + pos] = src[e] << 8;
            else spill_edge(src[e] << 8, d);
        }
    }
}

__device__ __forceinline__ ull f2add(ull a, ull b) {
    ull r;
    asm("add.rn.f32x2 %0, %1, %2;" : "=l"(r) : "l"(a), "l"(b));
    return r;
}
__device__ __forceinline__ ull f2mul(ull a, ull b) {
    ull r;
    asm("mul.rn.f32x2 %0, %1, %2;" : "=l"(r) : "l"(a), "l"(b));
    return r;
}

// One warp per node. Lane owns 8B (float2) of the 256B row.
// Per 4 edges: 1 uniform int4 idx load + 4 IMAD.WIDE + 4 LDG.64 gathers +
// 4 packed f32x2 adds into independent accumulators (~3.25 warp-instr/edge).
__global__ void __launch_bounds__(256)
aggregate_kernel(const char* __restrict__ xbase,
                 float2* __restrict__ out2, int N) {
    int n = (blockIdx.x * blockDim.x + threadIdx.x) >> 5;
    int lane = threadIdx.x & 31;
    if (n >= N) return;

    int count = g_cnt[n];
    int m = count < SLOTS ? count : SLOTS;
    const int4* row4 = (const int4*)&g_sorted[(size_t)n * SLOTS];
    const char* xlane = xbase + (lane << 3);

    ull a0 = 0, a1 = 0, a2 = 0, a3 = 0;

    int k = 0;
    for (; k + 4 <= m; k += 4) {
        int4 s = __ldg(&row4[k >> 2]);
        ull v0 = __ldg((const ull*)(xlane + (size_t)(unsigned)s.x));
        ull v1 = __ldg((const ull*)(xlane + (size_t)(unsigned)s.y));
        ull v2 = __ldg((const ull*)(xlane + (size_t)(unsigned)s.z));
        ull v3 = __ldg((const ull*)(xlane + (size_t)(unsigned)s.w));
        a0 = f2add(a0, v0);
        a1 = f2add(a1, v1);
        a2 = f2add(a2, v2);
        a3 = f2add(a3, v3);
    }
    {
        const int* row = (const int*)row4;
        for (; k < m; k++) {
            int s = __ldg(&row[k]);
            a0 = f2add(a0, __ldg((const ull*)(xlane + (size_t)(unsigned)s)));
        }
    }

    // Overflow fallback (cold: only if some node's degree exceeded SLOTS).
    if (count > SLOTS) {
        int oc = g_over_cnt[0];
        for (int i = 0; i < oc; i++) {
            if (g_over_tgt[i] == n) {
                int s = g_over_src[i];
                a0 = f2add(a0, __ldg((const ull*)(xlane + (size_t)(unsigned)s)));
            }
        }
    }

    a0 = f2add(f2add(a0, a1), f2add(a2, a3));

    float inv = count > 0 ? 1.0f / (float)count : 0.0f;
    ull inv2;
    asm("mov.b64 %0, {%1, %1};" : "=l"(inv2) : "f"(inv));
    ull o = f2mul(a0, inv2);

    unsigned int lo, hi;
    asm("mov.b64 {%0, %1}, %2;" : "=r"(lo), "=r"(hi) : "l"(o));
    float2 ov;
    ov.x = __uint_as_float(lo);
    ov.y = __uint_as_float(hi);
    out2[(size_t)n * 32 + lane] = ov;
}

extern "C" void kernel_launch(void* const* d_in, const int* in_sizes, int n_in,
                              void* d_out, int out_size) {
    const float* x = (const float*)d_in[0];
    const int* edge_idx = (const int*)d_in[1];

    int E = in_sizes[1] / 2;
    int N = out_size / F;

    const int* src = edge_idx;       // row 0
    const int* tgt = edge_idx + E;   // row 1

    // Zero scratch counters via memset nodes.
    void* cnt_ptr = nullptr;
    void* over_ptr = nullptr;
    cudaGetSymbolAddress(&cnt_ptr, g_cnt);
    cudaGetSymbolAddress(&over_ptr, g_over_cnt);
    cudaMemsetAsync(cnt_ptr, 0, (size_t)N * sizeof(int));
    cudaMemsetAsync(over_ptr, 0, sizeof(int));

    const int T = 256;

    int E4 = E / 4;
    int fill_blocks = (E4 + T - 1) / T;
    if (fill_blocks < 1) fill_blocks = 1;
    fill_kernel<<<fill_blocks, T>>>((const int4*)src, (const int4*)tgt, E4,
                                    src, tgt, E);

    long long total = (long long)N * 32;
    aggregate_kernel<<<(int)((total + T - 1) / T), T>>>(
        (const char*)x, (float2*)d_out, N);
}